// round 1
// baseline (speedup 1.0000x reference)
#include <cuda_runtime.h>
#include <cuda_bf16.h>
#include <cstdint>

// AFM forward, algebraically collapsed.
// softmax over size-1 axis == 1.0, so the attention net (attn_w_*, attn_h_*)
// is dead code. Output per row b:
//   x = sum_{i<j} emb_i . emb_j = 0.5 * (||sum_f emb_f||^2 - sum_f ||emb_f||^2)
//   out = sigmoid(x * out_kernel[0,0] + out_bias[0])
//
// Inputs (metadata order):
//   0: dense_x       [4096,13]  f32   (unused)
//   1: sparse_ids    [4096,26]  i32
//   2: embed_tables  [26,100000,16] f32
//   3: attn_w_kernel (unused)  4: attn_w_bias (unused)
//   5: attn_h_kernel (unused)  6: attn_h_bias (unused)
//   7: out_kernel    [1,1] f32
//   8: out_bias      [1]   f32
// Output: [4096,1] f32

#define B_ROWS   4096
#define N_SPARSE 26
#define VOCAB    100000
#define EMB      16

__global__ void __launch_bounds__(128) afm_gather_kernel(
    const int*    __restrict__ ids,     // [B, 26]
    const float4* __restrict__ table,   // [26, VOCAB, 4] as float4
    const float*  __restrict__ out_k,   // [1]
    const float*  __restrict__ out_b,   // [1]
    float*        __restrict__ out)     // [B]
{
    const int tid  = blockIdx.x * blockDim.x + threadIdx.x;
    const int row  = tid >> 2;     // 4 lanes cooperate on one batch row
    const int l4   = tid & 3;      // which float4 of the 16-float embedding
    if (row >= B_ROWS) return;

    const int* my_ids = ids + row * N_SPARSE;

    float4 S = make_float4(0.f, 0.f, 0.f, 0.f);
    float4 Q = make_float4(0.f, 0.f, 0.f, 0.f);

    // 26 independent 16B gathers per lane; addresses depend only on the id
    // loads, so the LSU can keep all of them in flight (MLP ~26).
    #pragma unroll
    for (int f = 0; f < N_SPARSE; ++f) {
        const int id = __ldg(my_ids + f);
        // table layout in float4 units: field stride = VOCAB*4, row stride = 4
        const float4 v = __ldg(table + (size_t)f * (VOCAB * 4) + (size_t)id * 4 + l4);
        S.x += v.x;        S.y += v.y;        S.z += v.z;        S.w += v.w;
        Q.x += v.x * v.x;  Q.y += v.y * v.y;  Q.z += v.z * v.z;  Q.w += v.w * v.w;
    }

    // per-lane partial of (sum_e S_e^2 - sum_e Q_e)
    float t = S.x * S.x + S.y * S.y + S.z * S.z + S.w * S.w
            - (Q.x + Q.y + Q.z + Q.w);

    // reduce across the 4 lanes of this row (lanes are adjacent in the warp)
    t += __shfl_xor_sync(0xffffffffu, t, 1);
    t += __shfl_xor_sync(0xffffffffu, t, 2);

    if (l4 == 0) {
        const float z = 0.5f * t * __ldg(out_k) + __ldg(out_b);
        out[row] = 1.0f / (1.0f + __expf(-z));
    }
}

extern "C" void kernel_launch(void* const* d_in, const int* in_sizes, int n_in,
                              void* d_out, int out_size)
{
    (void)in_sizes; (void)n_in; (void)out_size;
    const int*    ids   = (const int*)   d_in[1];
    const float4* table = (const float4*)d_in[2];
    const float*  out_k = (const float*) d_in[7];
    const float*  out_b = (const float*) d_in[8];
    float*        out   = (float*)       d_out;

    const int threads = 128;                       // 32 rows per block
    const int blocks  = (B_ROWS * 4 + threads - 1) / threads;  // 128 blocks
    afm_gather_kernel<<<blocks, threads>>>(ids, table, out_k, out_b, out);
}

// round 2
// speedup vs baseline: 1.2977x; 1.2977x over previous
#include <cuda_runtime.h>
#include <cuda_bf16.h>
#include <cstdint>

// AFM forward, algebraically collapsed (softmax over size-1 axis == 1):
//   x[b]  = sum_{i<j} emb_i . emb_j = 0.5*(||sum_f emb_f||^2 - sum_f ||emb_f||^2)
//   out[b] = sigmoid(x[b]*out_kernel + out_bias)
//
// Layout: ONE WARP PER ROW.
//   lane = fg*4 + l4 ; fg in [0,8) selects field-within-group, l4 selects
//   which float4 of the 16-float embedding. 4 field-groups cover 26 fields
//   (last group predicated). Per-lane work: <=4 independent 16B gathers.
// 4096 warps total -> ~28 warps/SM, hiding the ~577cy DRAM gather latency.

#define B_ROWS   4096
#define N_SPARSE 26
#define VOCAB    100000

__global__ void __launch_bounds__(256) afm_gather_kernel(
    const int*    __restrict__ ids,     // [B, 26]
    const float4* __restrict__ table,   // [26, VOCAB, 4] float4 units
    const float*  __restrict__ out_k,   // [1]
    const float*  __restrict__ out_b,   // [1]
    float*        __restrict__ out)     // [B]
{
    const unsigned FULL = 0xffffffffu;
    const int gtid = blockIdx.x * blockDim.x + threadIdx.x;
    const int row  = gtid >> 5;          // one warp per row
    const int lane = threadIdx.x & 31;
    if (row >= B_ROWS) return;

    // Coalesced id load: lanes 0..25 fetch this row's ids, shuffled out later.
    int my_id = 0;
    if (lane < N_SPARSE) my_id = __ldg(ids + row * N_SPARSE + lane);

    const int l4 = lane & 3;             // float4 slice 0..3
    const int fg = lane >> 2;            // field-in-group 0..7

    float4 S = make_float4(0.f, 0.f, 0.f, 0.f);
    float  q = 0.f;

    // 4 field groups; group 3 has only fields 24,25 (lanes 0..7 active).
    // All gathers are independent -> front-batched by ptxas (high MLP_p1).
    #pragma unroll
    for (int r = 0; r < 4; ++r) {
        const int  f   = r * 8 + fg;
        const bool act = (f < N_SPARSE);
        const int  id  = __shfl_sync(FULL, my_id, act ? f : 0);
        if (act) {
            const float4 v = __ldg(table + (size_t)f * (VOCAB * 4)
                                         + (size_t)id * 4 + l4);
            S.x += v.x; S.y += v.y; S.z += v.z; S.w += v.w;
            q   += v.x * v.x + v.y * v.y + v.z * v.z + v.w * v.w;
        }
    }

    // Reduce S over the field dimension (lane bits 2,3,4).
    #pragma unroll
    for (int d = 4; d <= 16; d <<= 1) {
        S.x += __shfl_xor_sync(FULL, S.x, d);
        S.y += __shfl_xor_sync(FULL, S.y, d);
        S.z += __shfl_xor_sync(FULL, S.z, d);
        S.w += __shfl_xor_sync(FULL, S.w, d);
    }
    // Reduce q over the whole warp.
    #pragma unroll
    for (int d = 1; d <= 16; d <<= 1)
        q += __shfl_xor_sync(FULL, q, d);

    // |S|^2 per slice, then sum over the 4 slices (lane bits 0,1).
    float s2 = S.x * S.x + S.y * S.y + S.z * S.z + S.w * S.w;
    s2 += __shfl_xor_sync(FULL, s2, 1);
    s2 += __shfl_xor_sync(FULL, s2, 2);

    if (lane == 0) {
        const float t = s2 - q;                  // == 2 * sum_{i<j} e_i.e_j
        const float z = 0.5f * t * __ldg(out_k) + __ldg(out_b);
        out[row] = 1.0f / (1.0f + __expf(-z));
    }
}

extern "C" void kernel_launch(void* const* d_in, const int* in_sizes, int n_in,
                              void* d_out, int out_size)
{
    (void)in_sizes; (void)n_in; (void)out_size;
    const int*    ids   = (const int*)   d_in[1];
    const float4* table = (const float4*)d_in[2];
    const float*  out_k = (const float*) d_in[7];
    const float*  out_b = (const float*) d_in[8];
    float*        out   = (float*)       d_out;

    const int threads = 256;                       // 8 warps = 8 rows / block
    const int blocks  = (B_ROWS * 32 + threads - 1) / threads;  // 512 blocks
    afm_gather_kernel<<<blocks, threads>>>(ids, table, out_k, out_b, out);
}